// round 3
// baseline (speedup 1.0000x reference)
#include <cuda_runtime.h>
#include <math.h>

#define EPS 1e-7f

// B=32, S=2048, D=1024
#define B_ 32
#define S_ 2048
#define D_ 1024

#define BSPLIT 8              // proj grid.y: batches per warp = B_/BSPLIT = 4
#define BPW (B_ / BSPLIT)     // 4
#define KSPLIT 2              // proj split-K factor
#define DH (D_ / KSPLIT)      // 512 d-elements per half

__device__ float g_projp[KSPLIT][B_][D_];  // partial proj per K-half
__device__ float g_sums[B_];               // per-batch sum of a (starts 0, reset each launch)
__device__ int   g_cnt[B_];                // per-batch block-arrival counters (reset each launch)

// ---------------------------------------------------------------------------
// Kernel 1: g_projp[h][b][e] = sum_{d in half h} M[e,d] * y[b,d]
// grid (D_/8, BSPLIT, KSPLIT), block 256 (8 warps). Warp -> one e, BPW batches,
// one D-half. M/y loaded as float4, lane-interleaved. Interleaved butterflies.
// ---------------------------------------------------------------------------
__global__ void proj_kernel(const float* __restrict__ y,
                            const float* __restrict__ M) {
    const int warp = threadIdx.x >> 5;
    const int lane = threadIdx.x & 31;
    const int e  = blockIdx.x * 8 + warp;
    const int b0 = blockIdx.y * BPW;
    const int h  = blockIdx.z;

    // M[e, h*512 : h*512+512] as float4: 128 float4s, 4 per lane
    const float4* Mv = reinterpret_cast<const float4*>(M + (size_t)e * D_) + h * (DH / 4);
    float4 m[4];
#pragma unroll
    for (int j = 0; j < 4; ++j) m[j] = Mv[j * 32 + lane];

    float acc[BPW];
#pragma unroll
    for (int bb = 0; bb < BPW; ++bb) acc[bb] = 0.0f;

#pragma unroll
    for (int bb = 0; bb < BPW; ++bb) {
        const float4* yv = reinterpret_cast<const float4*>(y + (size_t)(b0 + bb) * D_) + h * (DH / 4);
#pragma unroll
        for (int j = 0; j < 4; ++j) {
            float4 ya = yv[j * 32 + lane];
            acc[bb] = fmaf(m[j].x, ya.x, acc[bb]);
            acc[bb] = fmaf(m[j].y, ya.y, acc[bb]);
            acc[bb] = fmaf(m[j].z, ya.z, acc[bb]);
            acc[bb] = fmaf(m[j].w, ya.w, acc[bb]);
        }
    }

    // interleaved butterfly reductions (independent chains overlap)
#pragma unroll
    for (int off = 16; off > 0; off >>= 1) {
#pragma unroll
        for (int bb = 0; bb < BPW; ++bb)
            acc[bb] += __shfl_xor_sync(0xFFFFFFFFu, acc[bb], off);
    }

    if (lane < BPW) g_projp[h][b0 + lane][e] = acc[lane];
}

// ---------------------------------------------------------------------------
// Kernel 2 (fused): a[b,s] = exp(tanh(dot(x[b,s,:], proj[b,:]))) * mask[b,s],
// block partial-sums -> g_sums[b]; last block of each batch normalizes
// out[b,:] in place and resets g_sums/g_cnt for the next graph replay.
// grid: (S_/8, B_), block 256 (warp per s-row). x via float4.
// ---------------------------------------------------------------------------
__global__ void eij_kernel(const float* __restrict__ x,
                           const int* __restrict__ mask,
                           float* __restrict__ out) {
    const int b = blockIdx.y;
    const int warp = threadIdx.x >> 5;
    const int lane = threadIdx.x & 31;
    const int s = blockIdx.x * 8 + warp;

    __shared__ float4 sp[D_ / 4];          // proj[b] = sum of K-halves
    __shared__ float warp_partial[8];
    __shared__ int s_last;

    {
        const float4* p0 = reinterpret_cast<const float4*>(&g_projp[0][b][0]);
        const float4* p1 = reinterpret_cast<const float4*>(&g_projp[1][b][0]);
        float4 a0 = p0[threadIdx.x];
        float4 a1 = p1[threadIdx.x];
        sp[threadIdx.x] = make_float4(a0.x + a1.x, a0.y + a1.y, a0.z + a1.z, a0.w + a1.w);
    }
    __syncthreads();

    const float4* xv = reinterpret_cast<const float4*>(x + ((size_t)b * S_ + s) * D_);

    float acc = 0.0f;
#pragma unroll
    for (int j = 0; j < D_ / 128; ++j) {    // 8 iterations
        const int idx = j * 32 + lane;
        float4 xa = xv[idx];
        float4 pa = sp[idx];
        acc = fmaf(xa.x, pa.x, acc);
        acc = fmaf(xa.y, pa.y, acc);
        acc = fmaf(xa.z, pa.z, acc);
        acc = fmaf(xa.w, pa.w, acc);
    }
#pragma unroll
    for (int off = 16; off > 0; off >>= 1)
        acc += __shfl_xor_sync(0xFFFFFFFFu, acc, off);

    if (lane == 0) {
        float e = tanhf(acc);
        float a = __expf(e) * (float)mask[b * S_ + s];
        out[b * S_ + s] = a;
        warp_partial[warp] = a;
    }
    __syncthreads();

    if (threadIdx.x < 8) {
        float v = warp_partial[threadIdx.x];
#pragma unroll
        for (int off = 4; off > 0; off >>= 1)
            v += __shfl_xor_sync(0x000000FFu, v, off);
        if (threadIdx.x == 0) {
            atomicAdd(&g_sums[b], v);
            __threadfence();
            int old = atomicAdd(&g_cnt[b], 1);
            s_last = (old == (int)gridDim.x - 1);
        }
    }
    __syncthreads();

    // last block of this batch: normalize out[b,:] in place, reset state
    if (s_last) {
        __threadfence();  // acquire: see all other blocks' out/sum writes
        float inv = 1.0f / (g_sums[b] + EPS);
        float4* ov = reinterpret_cast<float4*>(out + (size_t)b * S_);
#pragma unroll
        for (int j = 0; j < S_ / 4 / 256; ++j) {   // 2 float4 per thread
            float4 v = ov[j * 256 + threadIdx.x];
            v.x *= inv; v.y *= inv; v.z *= inv; v.w *= inv;
            ov[j * 256 + threadIdx.x] = v;
        }
        if (threadIdx.x == 0) { g_sums[b] = 0.0f; g_cnt[b] = 0; }
    }
}

extern "C" void kernel_launch(void* const* d_in, const int* in_sizes, int n_in,
                              void* d_out, int out_size) {
    const float* x    = (const float*)d_in[0];   // [32, 2048, 1024]
    const float* y    = (const float*)d_in[1];   // [32, 1024]
    const int*   mask = (const int*)d_in[2];     // [32, 2048]
    const float* M    = (const float*)d_in[3];   // [1024, 1024]
    float* out = (float*)d_out;                  // [32, 2048]

    dim3 g1(D_ / 8, BSPLIT, KSPLIT);
    proj_kernel<<<g1, 256>>>(y, M);
    dim3 g2(S_ / 8, B_);
    eij_kernel<<<g2, 256>>>(x, mask, out);
}

// round 4
// speedup vs baseline: 1.2879x; 1.2879x over previous
#include <cuda_runtime.h>
#include <math.h>

#define EPS 1e-7f

// B=32, S=2048, D=1024
#define B_ 32
#define S_ 2048
#define D_ 1024

#define BSPLIT 8              // proj grid.y: batches per warp = B_/BSPLIT = 4
#define BPW (B_ / BSPLIT)     // 4
#define KSPLIT 4              // proj split-K factor
#define DH (D_ / KSPLIT)      // 256 d-elements per quarter

__device__ float g_projp[KSPLIT][B_][D_];  // partial proj per K-slice
__device__ float g_sums[B_];               // per-batch sum of a

// ---------------------------------------------------------------------------
// Kernel 1: g_projp[h][b][e] = sum_{d in slice h} M[e,d] * y[b,d]
// grid (D_/8, BSPLIT, KSPLIT), block 256 (8 warps). Warp -> one e, BPW batches,
// one 256-wide D-slice (2 float4 per lane). Also zeroes g_sums.
// ---------------------------------------------------------------------------
__global__ void proj_kernel(const float* __restrict__ y,
                            const float* __restrict__ M) {
    if (blockIdx.x == 0 && blockIdx.y == 0 && blockIdx.z == 0 && threadIdx.x < B_)
        g_sums[threadIdx.x] = 0.0f;

    const int warp = threadIdx.x >> 5;
    const int lane = threadIdx.x & 31;
    const int e  = blockIdx.x * 8 + warp;
    const int b0 = blockIdx.y * BPW;
    const int h  = blockIdx.z;

    // M[e, h*256 : h*256+256] as float4: 64 float4s, 2 per lane
    const float4* Mv = reinterpret_cast<const float4*>(M + (size_t)e * D_) + h * (DH / 4);
    float4 m0 = Mv[lane];
    float4 m1 = Mv[32 + lane];

    float acc[BPW];
#pragma unroll
    for (int bb = 0; bb < BPW; ++bb) acc[bb] = 0.0f;

#pragma unroll
    for (int bb = 0; bb < BPW; ++bb) {
        const float4* yv = reinterpret_cast<const float4*>(y + (size_t)(b0 + bb) * D_) + h * (DH / 4);
        float4 y0 = yv[lane];
        float4 y1 = yv[32 + lane];
        float a = 0.0f, c = 0.0f;
        a = fmaf(m0.x, y0.x, a); c = fmaf(m1.x, y1.x, c);
        a = fmaf(m0.y, y0.y, a); c = fmaf(m1.y, y1.y, c);
        a = fmaf(m0.z, y0.z, a); c = fmaf(m1.z, y1.z, c);
        a = fmaf(m0.w, y0.w, a); c = fmaf(m1.w, y1.w, c);
        acc[bb] = a + c;
    }

    // interleaved butterfly reductions (independent chains overlap)
#pragma unroll
    for (int off = 16; off > 0; off >>= 1) {
#pragma unroll
        for (int bb = 0; bb < BPW; ++bb)
            acc[bb] += __shfl_xor_sync(0xFFFFFFFFu, acc[bb], off);
    }

    if (lane < BPW) g_projp[h][b0 + lane][e] = acc[lane];
}

// ---------------------------------------------------------------------------
// Kernel 2: a[b,s] = exp(tanh(dot(x[b,s,:], proj[b,:]))) * mask[b,s]
// mask==0 rows skip the entire x read (output is exactly 0).
// Writes unnormalized a; block partial sums -> atomicAdd(g_sums[b]).
// grid: (S_/8, B_), block 256 (warp per s-row).
// ---------------------------------------------------------------------------
__global__ void eij_kernel(const float* __restrict__ x,
                           const int* __restrict__ mask,
                           float* __restrict__ out) {
    const int b = blockIdx.y;
    const int warp = threadIdx.x >> 5;
    const int lane = threadIdx.x & 31;
    const int s = blockIdx.x * 8 + warp;

    __shared__ float4 sp[D_ / 4];          // proj[b] = sum of K-slices
    __shared__ float warp_partial[8];

    // mask first: whole warp skips x if 0
    const int mk = mask[b * S_ + s];

    {
        float4 a0 = reinterpret_cast<const float4*>(&g_projp[0][b][0])[threadIdx.x];
        float4 a1 = reinterpret_cast<const float4*>(&g_projp[1][b][0])[threadIdx.x];
        float4 a2 = reinterpret_cast<const float4*>(&g_projp[2][b][0])[threadIdx.x];
        float4 a3 = reinterpret_cast<const float4*>(&g_projp[3][b][0])[threadIdx.x];
        sp[threadIdx.x] = make_float4(a0.x + a1.x + a2.x + a3.x,
                                      a0.y + a1.y + a2.y + a3.y,
                                      a0.z + a1.z + a2.z + a3.z,
                                      a0.w + a1.w + a2.w + a3.w);
    }
    __syncthreads();

    float a = 0.0f;
    if (mk != 0) {
        const float4* xv = reinterpret_cast<const float4*>(x + ((size_t)b * S_ + s) * D_);
        float acc = 0.0f;
#pragma unroll
        for (int j = 0; j < D_ / 128; ++j) {    // 8 iterations
            const int idx = j * 32 + lane;
            float4 xa = xv[idx];
            float4 pa = sp[idx];
            acc = fmaf(xa.x, pa.x, acc);
            acc = fmaf(xa.y, pa.y, acc);
            acc = fmaf(xa.z, pa.z, acc);
            acc = fmaf(xa.w, pa.w, acc);
        }
#pragma unroll
        for (int off = 16; off > 0; off >>= 1)
            acc += __shfl_xor_sync(0xFFFFFFFFu, acc, off);
        a = __expf(tanhf(acc));
    }

    if (lane == 0) {
        out[b * S_ + s] = a;
        warp_partial[warp] = a;
    }
    __syncthreads();

    if (threadIdx.x < 8) {
        float v = warp_partial[threadIdx.x];
#pragma unroll
        for (int off = 4; off > 0; off >>= 1)
            v += __shfl_xor_sync(0x000000FFu, v, off);
        if (threadIdx.x == 0) atomicAdd(&g_sums[b], v);
    }
}

// ---------------------------------------------------------------------------
// Kernel 3: out[b,s] /= (g_sums[b] + EPS)
// ---------------------------------------------------------------------------
__global__ void norm_kernel(float* __restrict__ out) {
    const int i = blockIdx.x * blockDim.x + threadIdx.x;
    if (i < B_ * S_) {
        const int b = i / S_;
        out[i] = out[i] / (g_sums[b] + EPS);
    }
}

extern "C" void kernel_launch(void* const* d_in, const int* in_sizes, int n_in,
                              void* d_out, int out_size) {
    const float* x    = (const float*)d_in[0];   // [32, 2048, 1024]
    const float* y    = (const float*)d_in[1];   // [32, 1024]
    const int*   mask = (const int*)d_in[2];     // [32, 2048]
    const float* M    = (const float*)d_in[3];   // [1024, 1024]
    float* out = (float*)d_out;                  // [32, 2048]

    dim3 g1(D_ / 8, BSPLIT, KSPLIT);
    proj_kernel<<<g1, 256>>>(y, M);
    dim3 g2(S_ / 8, B_);
    eij_kernel<<<g2, 256>>>(x, mask, out);
    norm_kernel<<<(B_ * S_ + 255) / 256, 256>>>(out);
}

// round 5
// speedup vs baseline: 1.3969x; 1.0846x over previous
#include <cuda_runtime.h>
#include <math.h>

#define EPS 1e-7f

// B=32, S=2048, D=1024
#define B_ 32
#define S_ 2048
#define D_ 1024

#define KSPLIT 4              // proj split-K factor
#define DH (D_ / KSPLIT)      // 256 d-elements per slice
#define BPW2 8                // batches per warp (y tile in regs)
#define EPW 8                 // e-rows per warp (M streamed)

__device__ float g_projp[KSPLIT][B_][D_];  // partial proj per K-slice
__device__ float g_sums[B_];               // per-batch sum of a

// ---------------------------------------------------------------------------
// Kernel 1: g_projp[h][b][e] = sum_{d in slice h} M[e,d] * y[b,d]
// grid (D_/(EPW*8), B_/BPW2, KSPLIT) = (16,4,4), block 256 (8 warps).
// Warp: y[8 batches][256-d slice] in registers (loaded once), streams 8 M-row
// slices, 8x8 dot-product tile. y traffic 16MB, M traffic 16MB (vs 132MB prev).
// ---------------------------------------------------------------------------
__global__ void proj_kernel(const float* __restrict__ y,
                            const float* __restrict__ M) {
    if (blockIdx.x == 0 && blockIdx.y == 0 && blockIdx.z == 0 && threadIdx.x < B_)
        g_sums[threadIdx.x] = 0.0f;

    const int warp = threadIdx.x >> 5;
    const int lane = threadIdx.x & 31;
    const int e0 = (blockIdx.x * 8 + warp) * EPW;
    const int b0 = blockIdx.y * BPW2;
    const int h  = blockIdx.z;

    // y tile: 8 batches x 256 d-slice, 2 float4 per lane per batch (64 regs)
    float4 yr[BPW2][2];
#pragma unroll
    for (int bb = 0; bb < BPW2; ++bb) {
        const float4* yv = reinterpret_cast<const float4*>(
            y + (size_t)(b0 + bb) * D_) + h * (DH / 4);
        yr[bb][0] = yv[lane];
        yr[bb][1] = yv[32 + lane];
    }

#pragma unroll 2
    for (int ee = 0; ee < EPW; ++ee) {
        const int e = e0 + ee;
        const float4* Mv = reinterpret_cast<const float4*>(
            M + (size_t)e * D_) + h * (DH / 4);
        float4 m0 = Mv[lane];
        float4 m1 = Mv[32 + lane];

        float acc[BPW2];
#pragma unroll
        for (int bb = 0; bb < BPW2; ++bb) {
            float a = 0.0f, c = 0.0f;
            a = fmaf(m0.x, yr[bb][0].x, a); c = fmaf(m1.x, yr[bb][1].x, c);
            a = fmaf(m0.y, yr[bb][0].y, a); c = fmaf(m1.y, yr[bb][1].y, c);
            a = fmaf(m0.z, yr[bb][0].z, a); c = fmaf(m1.z, yr[bb][1].z, c);
            a = fmaf(m0.w, yr[bb][0].w, a); c = fmaf(m1.w, yr[bb][1].w, c);
            acc[bb] = a + c;
        }

        // interleaved butterfly reductions (8 independent chains)
#pragma unroll
        for (int off = 16; off > 0; off >>= 1) {
#pragma unroll
            for (int bb = 0; bb < BPW2; ++bb)
                acc[bb] += __shfl_xor_sync(0xFFFFFFFFu, acc[bb], off);
        }

        if (lane < BPW2) g_projp[h][b0 + lane][e] = acc[lane];
    }
}

// ---------------------------------------------------------------------------
// Kernel 2: a[b,s] = exp(tanh(dot(x[b,s,:], proj[b,:]))) * mask[b,s]
// mask==0 rows skip the entire x read (output is exactly 0).
// grid: (S_/8, B_), block 256 (warp per s-row).
// ---------------------------------------------------------------------------
__global__ void eij_kernel(const float* __restrict__ x,
                           const int* __restrict__ mask,
                           float* __restrict__ out) {
    const int b = blockIdx.y;
    const int warp = threadIdx.x >> 5;
    const int lane = threadIdx.x & 31;
    const int s = blockIdx.x * 8 + warp;

    __shared__ float4 sp[D_ / 4];          // proj[b] = sum of K-slices
    __shared__ float warp_partial[8];

    const int mk = mask[b * S_ + s];

    {
        float4 a0 = reinterpret_cast<const float4*>(&g_projp[0][b][0])[threadIdx.x];
        float4 a1 = reinterpret_cast<const float4*>(&g_projp[1][b][0])[threadIdx.x];
        float4 a2 = reinterpret_cast<const float4*>(&g_projp[2][b][0])[threadIdx.x];
        float4 a3 = reinterpret_cast<const float4*>(&g_projp[3][b][0])[threadIdx.x];
        sp[threadIdx.x] = make_float4(a0.x + a1.x + a2.x + a3.x,
                                      a0.y + a1.y + a2.y + a3.y,
                                      a0.z + a1.z + a2.z + a3.z,
                                      a0.w + a1.w + a2.w + a3.w);
    }
    __syncthreads();

    float a = 0.0f;
    if (mk != 0) {
        const float4* xv = reinterpret_cast<const float4*>(x + ((size_t)b * S_ + s) * D_);
        float acc = 0.0f;
#pragma unroll
        for (int j = 0; j < D_ / 128; ++j) {    // 8 iterations
            const int idx = j * 32 + lane;
            float4 xa = xv[idx];
            float4 pa = sp[idx];
            acc = fmaf(xa.x, pa.x, acc);
            acc = fmaf(xa.y, pa.y, acc);
            acc = fmaf(xa.z, pa.z, acc);
            acc = fmaf(xa.w, pa.w, acc);
        }
#pragma unroll
        for (int off = 16; off > 0; off >>= 1)
            acc += __shfl_xor_sync(0xFFFFFFFFu, acc, off);
        a = __expf(tanhf(acc));
    }

    if (lane == 0) {
        out[b * S_ + s] = a;
        warp_partial[warp] = a;
    }
    __syncthreads();

    if (threadIdx.x < 8) {
        float v = warp_partial[threadIdx.x];
#pragma unroll
        for (int off = 4; off > 0; off >>= 1)
            v += __shfl_xor_sync(0x000000FFu, v, off);
        if (threadIdx.x == 0) atomicAdd(&g_sums[b], v);
    }
}

// ---------------------------------------------------------------------------
// Kernel 3: out[b,s] /= (g_sums[b] + EPS)
// ---------------------------------------------------------------------------
__global__ void norm_kernel(float* __restrict__ out) {
    const int i = blockIdx.x * blockDim.x + threadIdx.x;
    if (i < B_ * S_) {
        const int b = i / S_;
        out[i] = out[i] / (g_sums[b] + EPS);
    }
}

extern "C" void kernel_launch(void* const* d_in, const int* in_sizes, int n_in,
                              void* d_out, int out_size) {
    const float* x    = (const float*)d_in[0];   // [32, 2048, 1024]
    const float* y    = (const float*)d_in[1];   // [32, 1024]
    const int*   mask = (const int*)d_in[2];     // [32, 2048]
    const float* M    = (const float*)d_in[3];   // [1024, 1024]
    float* out = (float*)d_out;                  // [32, 2048]

    dim3 g1(D_ / (EPW * 8), B_ / BPW2, KSPLIT);
    proj_kernel<<<g1, 256>>>(y, M);
    dim3 g2(S_ / 8, B_);
    eij_kernel<<<g2, 256>>>(x, mask, out);
    norm_kernel<<<(B_ * S_ + 255) / 256, 256>>>(out);
}

// round 6
// speedup vs baseline: 1.4740x; 1.0552x over previous
#include <cuda_runtime.h>
#include <math.h>

#define EPS 1e-7f

// B=32, S=2048, D=1024
#define B_ 32
#define S_ 2048
#define D_ 1024

#define KSPLIT 4              // proj split-K factor
#define DH (D_ / KSPLIT)      // 256 d-elements per slice
#define BPW2 4                // batches per warp (y tile in regs)
#define EPW 8                 // e-rows per warp (M streamed)

__device__ float g_proj[B_][D_];   // merged proj (atomicAdd; zeroed by norm for next replay)
__device__ float g_sums[B_];       // per-batch sum of a

// ---------------------------------------------------------------------------
// Kernel 1: g_proj[b][e] += sum_{d in slice h} M[e,d] * y[b,d]   (RED.ADD)
// grid (D_/(EPW*8), B_/BPW2, KSPLIT) = (16,8,4), block 256 (8 warps).
// Warp: y[4 batches][256-d slice] in regs, streams 8 M-row slices.
// 4096 warps, ~48 regs -> latency actually hidden this time.
// ---------------------------------------------------------------------------
__global__ void proj_kernel(const float* __restrict__ y,
                            const float* __restrict__ M) {
    if (blockIdx.x == 0 && blockIdx.y == 0 && blockIdx.z == 0 && threadIdx.x < B_)
        g_sums[threadIdx.x] = 0.0f;

    const int warp = threadIdx.x >> 5;
    const int lane = threadIdx.x & 31;
    const int e0 = (blockIdx.x * 8 + warp) * EPW;
    const int b0 = blockIdx.y * BPW2;
    const int h  = blockIdx.z;

    // y tile: 4 batches x 256 d-slice, 2 float4 per lane per batch (32 regs)
    float4 yr[BPW2][2];
#pragma unroll
    for (int bb = 0; bb < BPW2; ++bb) {
        const float4* yv = reinterpret_cast<const float4*>(
            y + (size_t)(b0 + bb) * D_) + h * (DH / 4);
        yr[bb][0] = yv[lane];
        yr[bb][1] = yv[32 + lane];
    }

#pragma unroll 2
    for (int ee = 0; ee < EPW; ++ee) {
        const int e = e0 + ee;
        const float4* Mv = reinterpret_cast<const float4*>(
            M + (size_t)e * D_) + h * (DH / 4);
        float4 m0 = Mv[lane];
        float4 m1 = Mv[32 + lane];

        float acc[BPW2];
#pragma unroll
        for (int bb = 0; bb < BPW2; ++bb) {
            float a = 0.0f, c = 0.0f;
            a = fmaf(m0.x, yr[bb][0].x, a); c = fmaf(m1.x, yr[bb][1].x, c);
            a = fmaf(m0.y, yr[bb][0].y, a); c = fmaf(m1.y, yr[bb][1].y, c);
            a = fmaf(m0.z, yr[bb][0].z, a); c = fmaf(m1.z, yr[bb][1].z, c);
            a = fmaf(m0.w, yr[bb][0].w, a); c = fmaf(m1.w, yr[bb][1].w, c);
            acc[bb] = a + c;
        }

        // interleaved butterfly reductions (4 independent chains)
#pragma unroll
        for (int off = 16; off > 0; off >>= 1) {
#pragma unroll
            for (int bb = 0; bb < BPW2; ++bb)
                acc[bb] += __shfl_xor_sync(0xFFFFFFFFu, acc[bb], off);
        }

        if (lane < BPW2) atomicAdd(&g_proj[b0 + lane][e], acc[lane]);
    }
}

// ---------------------------------------------------------------------------
// Kernel 2: a[b,s] = exp(tanh(dot(x[b,s,:], proj[b,:]))) * mask[b,s]
// mask==0 rows skip the entire x read (output is exactly 0).
// grid: (S_/8, B_), block 256 (warp per s-row). Stages merged g_proj (4KB).
// ---------------------------------------------------------------------------
__global__ void eij_kernel(const float* __restrict__ x,
                           const int* __restrict__ mask,
                           float* __restrict__ out) {
    const int b = blockIdx.y;
    const int warp = threadIdx.x >> 5;
    const int lane = threadIdx.x & 31;
    const int s = blockIdx.x * 8 + warp;

    __shared__ float4 sp[D_ / 4];
    __shared__ float warp_partial[8];

    const int mk = mask[b * S_ + s];

    sp[threadIdx.x] = reinterpret_cast<const float4*>(&g_proj[b][0])[threadIdx.x];
    __syncthreads();

    float a = 0.0f;
    if (mk != 0) {
        const float4* xv = reinterpret_cast<const float4*>(x + ((size_t)b * S_ + s) * D_);
        float acc = 0.0f;
#pragma unroll
        for (int j = 0; j < D_ / 128; ++j) {    // 8 iterations
            const int idx = j * 32 + lane;
            float4 xa = xv[idx];
            float4 pa = sp[idx];
            acc = fmaf(xa.x, pa.x, acc);
            acc = fmaf(xa.y, pa.y, acc);
            acc = fmaf(xa.z, pa.z, acc);
            acc = fmaf(xa.w, pa.w, acc);
        }
#pragma unroll
        for (int off = 16; off > 0; off >>= 1)
            acc += __shfl_xor_sync(0xFFFFFFFFu, acc, off);
        a = __expf(tanhf(acc));
    }

    if (lane == 0) {
        out[b * S_ + s] = a;
        warp_partial[warp] = a;
    }
    __syncthreads();

    if (threadIdx.x < 8) {
        float v = warp_partial[threadIdx.x];
#pragma unroll
        for (int off = 4; off > 0; off >>= 1)
            v += __shfl_xor_sync(0x000000FFu, v, off);
        if (threadIdx.x == 0) atomicAdd(&g_sums[b], v);
    }
}

// ---------------------------------------------------------------------------
// Kernel 3: out[b,s] /= (g_sums[b] + EPS); also zero g_proj for next replay.
// ---------------------------------------------------------------------------
__global__ void norm_kernel(float* __restrict__ out) {
    const int i = blockIdx.x * blockDim.x + threadIdx.x;
    if (i < B_ * S_) {
        const int b = i / S_;
        out[i] = out[i] / (g_sums[b] + EPS);
    }
    if (i < B_ * D_) reinterpret_cast<float*>(g_proj)[i] = 0.0f;
}

extern "C" void kernel_launch(void* const* d_in, const int* in_sizes, int n_in,
                              void* d_out, int out_size) {
    const float* x    = (const float*)d_in[0];   // [32, 2048, 1024]
    const float* y    = (const float*)d_in[1];   // [32, 1024]
    const int*   mask = (const int*)d_in[2];     // [32, 2048]
    const float* M    = (const float*)d_in[3];   // [1024, 1024]
    float* out = (float*)d_out;                  // [32, 2048]

    dim3 g1(D_ / (EPW * 8), B_ / BPW2, KSPLIT);
    proj_kernel<<<g1, 256>>>(y, M);
    dim3 g2(S_ / 8, B_);
    eij_kernel<<<g2, 256>>>(x, mask, out);
    norm_kernel<<<(B_ * S_ + 255) / 256, 256>>>(out);
}

// round 7
// speedup vs baseline: 1.7328x; 1.1756x over previous
#include <cuda_runtime.h>
#include <math.h>

#define EPS 1e-7f

// B=32, S=2048, D=1024
#define B_ 32
#define S_ 2048
#define D_ 1024

#define KSPLIT 4              // proj split-K factor
#define DH (D_ / KSPLIT)      // 256 d-elements per slice
#define BPW2 4                // batches per warp (y tile in regs)
#define EPW 8                 // e-rows per warp (M streamed)

__device__ float g_proj[B_][D_];   // merged proj (atomicAdd; zeroed by norm for next replay)
__device__ float g_sums[B_];       // per-batch sum of a

// ---------------------------------------------------------------------------
// Kernel 1: g_proj[b][e] += sum_{d in slice h} M[e,d] * y[b,d]
// grid (16, 8, 4), block 256 (8 warps). Warp: 32 dots (8e x 4b) over a 256-d
// slice, all accumulators live; ONE log-tree multi-value reduction (31 SHFL
// instead of 160) leaves dot l on lane l. One scattered RED.ADD per lane.
// ---------------------------------------------------------------------------
__global__ void proj_kernel(const float* __restrict__ y,
                            const float* __restrict__ M) {
    if (blockIdx.x == 0 && blockIdx.y == 0 && blockIdx.z == 0 && threadIdx.x < B_)
        g_sums[threadIdx.x] = 0.0f;

    const int warp = threadIdx.x >> 5;
    const int lane = threadIdx.x & 31;
    const int e0 = (blockIdx.x * 8 + warp) * EPW;
    const int b0 = blockIdx.y * BPW2;
    const int h  = blockIdx.z;

    // y tile: 4 batches x 256 d-slice, 2 float4 per lane per batch
    float4 yr[BPW2][2];
#pragma unroll
    for (int bb = 0; bb < BPW2; ++bb) {
        const float4* yv = reinterpret_cast<const float4*>(
            y + (size_t)(b0 + bb) * D_) + h * (DH / 4);
        yr[bb][0] = yv[lane];
        yr[bb][1] = yv[32 + lane];
    }

    float acc[32];   // acc[ee*4+bb]
#pragma unroll
    for (int ee = 0; ee < EPW; ++ee) {
        const float4* Mv = reinterpret_cast<const float4*>(
            M + (size_t)(e0 + ee) * D_) + h * (DH / 4);
        float4 m0 = Mv[lane];
        float4 m1 = Mv[32 + lane];
#pragma unroll
        for (int bb = 0; bb < BPW2; ++bb) {
            float a = 0.0f, c = 0.0f;
            a = fmaf(m0.x, yr[bb][0].x, a); c = fmaf(m1.x, yr[bb][1].x, c);
            a = fmaf(m0.y, yr[bb][0].y, a); c = fmaf(m1.y, yr[bb][1].y, c);
            a = fmaf(m0.z, yr[bb][0].z, a); c = fmaf(m1.z, yr[bb][1].z, c);
            a = fmaf(m0.w, yr[bb][0].w, a); c = fmaf(m1.w, yr[bb][1].w, c);
            acc[ee * 4 + bb] = a + c;
        }
    }

    // multi-value tree reduction: 32 values x 32 lanes -> dot l on lane l.
    // step off: lanes with (lane&off) keep group acc[j+off] (index bit set),
    // others keep acc[j]; each adds the partner's copy of its kept group.
#pragma unroll
    for (int off = 16; off > 0; off >>= 1) {
#pragma unroll
        for (int j = 0; j < off; ++j) {
            float send = (lane & off) ? acc[j] : acc[j + off];
            float other = __shfl_xor_sync(0xFFFFFFFFu, send, off);
            acc[j] = ((lane & off) ? acc[j + off] : acc[j]) + other;
        }
    }
    // dot index v = ee*4+bb == lane  ->  bb = lane&3, ee = lane>>2
    atomicAdd(&g_proj[b0 + (lane & 3)][e0 + (lane >> 2)], acc[0]);
}

// ---------------------------------------------------------------------------
// Kernel 2: a[b,s] = exp(tanh(dot(x[b,s,:], proj[b,:]))) * mask[b,s]
// Warp handles TWO consecutive s-rows (8KB contiguous when both live);
// mask==0 rows skip their x read entirely. x via __ldcs (streaming).
// grid: (S_/16, B_), block 256.
// ---------------------------------------------------------------------------
__global__ void eij_kernel(const float* __restrict__ x,
                           const int* __restrict__ mask,
                           float* __restrict__ out) {
    const int b = blockIdx.y;
    const int warp = threadIdx.x >> 5;
    const int lane = threadIdx.x & 31;
    const int s0 = blockIdx.x * 16 + warp * 2;

    __shared__ float4 sp[D_ / 4];
    __shared__ float warp_partial[8];

    const int mk0 = mask[b * S_ + s0];
    const int mk1 = mask[b * S_ + s0 + 1];

    sp[threadIdx.x] = reinterpret_cast<const float4*>(&g_proj[b][0])[threadIdx.x];
    __syncthreads();

    float d0 = 0.0f, d1 = 0.0f;
    if (mk0 != 0) {
        const float4* xv = reinterpret_cast<const float4*>(x + ((size_t)b * S_ + s0) * D_);
#pragma unroll
        for (int j = 0; j < D_ / 128; ++j) {
            const int idx = j * 32 + lane;
            float4 xa = __ldcs(xv + idx);
            float4 pa = sp[idx];
            d0 = fmaf(xa.x, pa.x, d0);
            d0 = fmaf(xa.y, pa.y, d0);
            d0 = fmaf(xa.z, pa.z, d0);
            d0 = fmaf(xa.w, pa.w, d0);
        }
    }
    if (mk1 != 0) {
        const float4* xv = reinterpret_cast<const float4*>(x + ((size_t)b * S_ + s0 + 1) * D_);
#pragma unroll
        for (int j = 0; j < D_ / 128; ++j) {
            const int idx = j * 32 + lane;
            float4 xa = __ldcs(xv + idx);
            float4 pa = sp[idx];
            d1 = fmaf(xa.x, pa.x, d1);
            d1 = fmaf(xa.y, pa.y, d1);
            d1 = fmaf(xa.z, pa.z, d1);
            d1 = fmaf(xa.w, pa.w, d1);
        }
    }
#pragma unroll
    for (int off = 16; off > 0; off >>= 1) {
        d0 += __shfl_xor_sync(0xFFFFFFFFu, d0, off);
        d1 += __shfl_xor_sync(0xFFFFFFFFu, d1, off);
    }

    float a0 = (mk0 != 0) ? __expf(tanhf(d0)) : 0.0f;
    float a1 = (mk1 != 0) ? __expf(tanhf(d1)) : 0.0f;

    if (lane == 0) {
        reinterpret_cast<float2*>(out)[(b * S_ + s0) >> 1] = make_float2(a0, a1);
        warp_partial[warp] = a0 + a1;
    }
    __syncthreads();

    if (threadIdx.x < 8) {
        float v = warp_partial[threadIdx.x];
#pragma unroll
        for (int off = 4; off > 0; off >>= 1)
            v += __shfl_xor_sync(0x000000FFu, v, off);
        if (threadIdx.x == 0) atomicAdd(&g_sums[b], v);
    }
}

// ---------------------------------------------------------------------------
// Kernel 3: out[b,s] /= (g_sums[b] + EPS); also zero g_proj for next replay.
// ---------------------------------------------------------------------------
__global__ void norm_kernel(float* __restrict__ out) {
    const int i = blockIdx.x * blockDim.x + threadIdx.x;
    if (i < B_ * S_) {
        const int b = i / S_;
        out[i] = out[i] / (g_sums[b] + EPS);
    }
    if (i < B_ * D_) reinterpret_cast<float*>(g_proj)[i] = 0.0f;
}

extern "C" void kernel_launch(void* const* d_in, const int* in_sizes, int n_in,
                              void* d_out, int out_size) {
    const float* x    = (const float*)d_in[0];   // [32, 2048, 1024]
    const float* y    = (const float*)d_in[1];   // [32, 1024]
    const int*   mask = (const int*)d_in[2];     // [32, 2048]
    const float* M    = (const float*)d_in[3];   // [1024, 1024]
    float* out = (float*)d_out;                  // [32, 2048]

    dim3 g1(D_ / (EPW * 8), B_ / BPW2, KSPLIT);
    proj_kernel<<<g1, 256>>>(y, M);
    dim3 g2(S_ / 16, B_);
    eij_kernel<<<g2, 256>>>(x, mask, out);
    norm_kernel<<<(B_ * S_ + 255) / 256, 256>>>(out);
}

// round 8
// speedup vs baseline: 1.7462x; 1.0077x over previous
#include <cuda_runtime.h>
#include <math.h>

#define EPS 1e-7f

// B=32, S=2048, D=1024
#define B_ 32
#define S_ 2048
#define D_ 1024

#define KSPLIT 8              // proj split-K factor
#define DH (D_ / KSPLIT)      // 128 d-elements per slice
#define BPW2 4                // batches per warp (y tile in regs)
#define EPW 8                 // e-rows per warp (M streamed)

__device__ float g_proj[B_][D_];   // merged proj (atomicAdd; zeroed by norm for next replay)
__device__ float g_sums[B_];       // per-batch sum of a

// ---------------------------------------------------------------------------
// Kernel 1: g_proj[b][e] += sum_{d in slice h} M[e,d] * y[b,d]
// grid (16, 8, 8) = 1024 blocks, 256 thr (8 warps). Warp: 32 dots (8e x 4b)
// over a 128-d slice (1 float4/lane/operand); one log-tree multi-value
// reduction (31 SHFL) leaves dot l on lane l; scattered RED.ADD per lane.
// ---------------------------------------------------------------------------
__global__ void proj_kernel(const float* __restrict__ y,
                            const float* __restrict__ M) {
    if (blockIdx.x == 0 && blockIdx.y == 0 && blockIdx.z == 0 && threadIdx.x < B_)
        g_sums[threadIdx.x] = 0.0f;

    const int warp = threadIdx.x >> 5;
    const int lane = threadIdx.x & 31;
    const int e0 = (blockIdx.x * 8 + warp) * EPW;
    const int b0 = blockIdx.y * BPW2;
    const int h  = blockIdx.z;

    // y tile: 4 batches x 128-d slice, 1 float4 per lane per batch
    float4 yr[BPW2];
#pragma unroll
    for (int bb = 0; bb < BPW2; ++bb) {
        const float4* yv = reinterpret_cast<const float4*>(
            y + (size_t)(b0 + bb) * D_) + h * (DH / 4);
        yr[bb] = yv[lane];
    }

    float acc[32];   // acc[ee*4+bb]
#pragma unroll
    for (int ee = 0; ee < EPW; ++ee) {
        const float4* Mv = reinterpret_cast<const float4*>(
            M + (size_t)(e0 + ee) * D_) + h * (DH / 4);
        float4 m = Mv[lane];
#pragma unroll
        for (int bb = 0; bb < BPW2; ++bb) {
            float a = 0.0f;
            a = fmaf(m.x, yr[bb].x, a);
            a = fmaf(m.y, yr[bb].y, a);
            a = fmaf(m.z, yr[bb].z, a);
            a = fmaf(m.w, yr[bb].w, a);
            acc[ee * 4 + bb] = a;
        }
    }

    // multi-value tree reduction: 32 values x 32 lanes -> dot l on lane l
#pragma unroll
    for (int off = 16; off > 0; off >>= 1) {
#pragma unroll
        for (int j = 0; j < off; ++j) {
            float send = (lane & off) ? acc[j] : acc[j + off];
            float other = __shfl_xor_sync(0xFFFFFFFFu, send, off);
            acc[j] = ((lane & off) ? acc[j + off] : acc[j]) + other;
        }
    }
    // dot index v = ee*4+bb == lane  ->  bb = lane&3, ee = lane>>2
    atomicAdd(&g_proj[b0 + (lane & 3)][e0 + (lane >> 2)], acc[0]);
}

// ---------------------------------------------------------------------------
// Kernel 2: a[b,s] = exp(tanh(dot(x[b,s,:], proj[b,:]))) * mask[b,s]
// Warp handles TWO consecutive s-rows; mask==0 rows skip their x read.
// x via __ldcs (streaming). grid: (S_/16, B_), block 256.
// ---------------------------------------------------------------------------
__global__ void eij_kernel(const float* __restrict__ x,
                           const int* __restrict__ mask,
                           float* __restrict__ out) {
    const int b = blockIdx.y;
    const int warp = threadIdx.x >> 5;
    const int lane = threadIdx.x & 31;
    const int s0 = blockIdx.x * 16 + warp * 2;

    __shared__ float4 sp[D_ / 4];
    __shared__ float warp_partial[8];

    const int mk0 = mask[b * S_ + s0];
    const int mk1 = mask[b * S_ + s0 + 1];

    sp[threadIdx.x] = reinterpret_cast<const float4*>(&g_proj[b][0])[threadIdx.x];
    __syncthreads();

    float d0 = 0.0f, d1 = 0.0f;
    if (mk0 != 0) {
        const float4* xv = reinterpret_cast<const float4*>(x + ((size_t)b * S_ + s0) * D_);
#pragma unroll
        for (int j = 0; j < D_ / 128; ++j) {
            const int idx = j * 32 + lane;
            float4 xa = __ldcs(xv + idx);
            float4 pa = sp[idx];
            d0 = fmaf(xa.x, pa.x, d0);
            d0 = fmaf(xa.y, pa.y, d0);
            d0 = fmaf(xa.z, pa.z, d0);
            d0 = fmaf(xa.w, pa.w, d0);
        }
    }
    if (mk1 != 0) {
        const float4* xv = reinterpret_cast<const float4*>(x + ((size_t)b * S_ + s0 + 1) * D_);
#pragma unroll
        for (int j = 0; j < D_ / 128; ++j) {
            const int idx = j * 32 + lane;
            float4 xa = __ldcs(xv + idx);
            float4 pa = sp[idx];
            d1 = fmaf(xa.x, pa.x, d1);
            d1 = fmaf(xa.y, pa.y, d1);
            d1 = fmaf(xa.z, pa.z, d1);
            d1 = fmaf(xa.w, pa.w, d1);
        }
    }
#pragma unroll
    for (int off = 16; off > 0; off >>= 1) {
        d0 += __shfl_xor_sync(0xFFFFFFFFu, d0, off);
        d1 += __shfl_xor_sync(0xFFFFFFFFu, d1, off);
    }

    float a0 = (mk0 != 0) ? __expf(tanhf(d0)) : 0.0f;
    float a1 = (mk1 != 0) ? __expf(tanhf(d1)) : 0.0f;

    if (lane == 0) {
        reinterpret_cast<float2*>(out)[(b * S_ + s0) >> 1] = make_float2(a0, a1);
        warp_partial[warp] = a0 + a1;
    }
    __syncthreads();

    if (threadIdx.x < 8) {
        float v = warp_partial[threadIdx.x];
#pragma unroll
        for (int off = 4; off > 0; off >>= 1)
            v += __shfl_xor_sync(0x000000FFu, v, off);
        if (threadIdx.x == 0) atomicAdd(&g_sums[b], v);
    }
}

// ---------------------------------------------------------------------------
// Kernel 3: out /= (sum + EPS) via float4; zero g_proj for next replay.
// grid 64 x 256 threads: thread i handles out float4 i and g_proj float4s.
// ---------------------------------------------------------------------------
__global__ void norm_kernel(float* __restrict__ out) {
    const int i = blockIdx.x * blockDim.x + threadIdx.x;   // 0..16383
    const int b = i / (S_ / 4);
    float inv = 1.0f / (g_sums[b] + EPS);
    float4 v = reinterpret_cast<float4*>(out)[i];
    v.x *= inv; v.y *= inv; v.z *= inv; v.w *= inv;
    reinterpret_cast<float4*>(out)[i] = v;
    // zero g_proj: B*D/4 = 8192 float4s, first 8192 threads do one each
    if (i < B_ * D_ / 4)
        reinterpret_cast<float4*>(g_proj)[i] = make_float4(0.f, 0.f, 0.f, 0.f);
}

extern "C" void kernel_launch(void* const* d_in, const int* in_sizes, int n_in,
                              void* d_out, int out_size) {
    const float* x    = (const float*)d_in[0];   // [32, 2048, 1024]
    const float* y    = (const float*)d_in[1];   // [32, 1024]
    const int*   mask = (const int*)d_in[2];     // [32, 2048]
    const float* M    = (const float*)d_in[3];   // [1024, 1024]
    float* out = (float*)d_out;                  // [32, 2048]

    dim3 g1(D_ / (EPW * 8), B_ / BPW2, KSPLIT);
    proj_kernel<<<g1, 256>>>(y, M);
    dim3 g2(S_ / 16, B_);
    eij_kernel<<<g2, 256>>>(x, mask, out);
    norm_kernel<<<(B_ * S_ / 4) / 256, 256>>>(out);
}